// round 9
// baseline (speedup 1.0000x reference)
#include <cuda_runtime.h>
#include <cuda_fp16.h>
#include <stdint.h>

// Problem constants (fixed by the reference)
#define BATCH 1024
#define IN_SIZE 2048
#define OUT_SIZE 2048
#define EMAX 131072

#define NG 16                // n-groups of 128 outputs  (gemm grid.x)
#define NKC 32               // k-chunks of 64 inputs
#define NBUCKET (NG * NKC)   // 512 sort buckets
#define NEBLK 64             // edge chunks for the build

#define BK 64                // halves per K chunk (128B SW128 row)
#define TILEB 16384          // 128 rows x 128 bytes
#define A_STAGES 3
#define SMEM_A (A_STAGES * TILEB)          // 48 KB
#define SMEM_TOTAL (SMEM_A + 2 * TILEB)    // + 32 KB B double buffer = 80 KB

// -------- device scratch (no allocations allowed) --------
__device__ __half   g_xh[BATCH * IN_SIZE];     // 4 MB x fp16 [batch][in]
__device__ int      g_cntM[NEBLK][NBUCKET];
__device__ int      g_curM[NEBLK][NBUCKET];
__device__ int      g_boff[NBUCKET + 1];
__device__ unsigned g_rec[EMAX];               // n_local<<22 | k_local<<16 | w_fp16

__device__ __forceinline__ int fetch_idx(const void* p, int e, int is64) {
    if (is64) return (int)(((const long long*)p)[e]);
    return ((const int*)p)[e];
}

// per-block index-dtype detection (no cross-kernel dependency)
__device__ __forceinline__ int detect64(const void* in_idx, int E) {
    __shared__ int s_is64;
    if (threadIdx.x < 32) {
        const long long* q = (const long long*)in_idx;
        long long v = ((int)threadIdx.x < E) ? q[threadIdx.x] : 0;
        bool bad = (v < 0 || v >= IN_SIZE);
        unsigned m = __ballot_sync(0xFFFFFFFFu, bad);
        if (threadIdx.x == 0) s_is64 = (m == 0) ? 1 : 0;
    }
    __syncthreads();
    return s_is64;
}

// ---------------- asm helpers ----------------
__device__ __forceinline__ uint32_t smem_u32(const void* p) {
    uint32_t a;
    asm("{ .reg .u64 t; cvta.to.shared.u64 t, %1; cvt.u32.u64 %0, t; }"
        : "=r"(a) : "l"(p));
    return a;
}
#define SWZ128(off) ((off) ^ (((off) >> 3) & 0x70))
#define CP_ASYNC16(dst, src) \
    asm volatile("cp.async.cg.shared.global [%0], [%1], 16;" :: "r"(dst), "l"(src))
#define CP_COMMIT() asm volatile("cp.async.commit_group;" ::: "memory")
#define CP_WAIT1()  asm volatile("cp.async.wait_group 1;" ::: "memory")
#define LDSM4(r0, r1, r2, r3, a)                                               \
    asm volatile("ldmatrix.sync.aligned.m8n8.x4.shared.b16 {%0,%1,%2,%3}, [%4];" \
                 : "=r"(r0), "=r"(r1), "=r"(r2), "=r"(r3) : "r"(a))
#define MMA16816(c, a, b0, b1)                                                 \
    asm volatile(                                                              \
        "mma.sync.aligned.m16n8k16.row.col.f32.f16.f16.f32 "                   \
        "{%0,%1,%2,%3}, {%4,%5,%6,%7}, {%8,%9}, {%0,%1,%2,%3};"                \
        : "+f"(c[0]), "+f"(c[1]), "+f"(c[2]), "+f"(c[3])                       \
        : "r"(a[0]), "r"(a[1]), "r"(a[2]), "r"(a[3]), "r"(b0), "r"(b1))

// -------- 1. fused: convert x (blocks 0..511) + bucket histogram (512..575) -
__global__ void __launch_bounds__(256) prep_hist_kernel(
    const float* __restrict__ x, const void* in_idx, const void* out_idx, int E) {
    if (blockIdx.x < 512) {
        int t = blockIdx.x * 256 + threadIdx.x;   // 131072 threads x 4 float4
#pragma unroll
        for (int r = 0; r < 4; r++) {
            int q = t + r * 131072;
            float4 v = reinterpret_cast<const float4*>(x)[q];
            __half2 h0 = __floats2half2_rn(v.x, v.y);
            __half2 h1 = __floats2half2_rn(v.z, v.w);
            reinterpret_cast<__half2*>(g_xh)[2 * q]     = h0;
            reinterpret_cast<__half2*>(g_xh)[2 * q + 1] = h1;
        }
    } else {
        int b = blockIdx.x - 512;
        __shared__ int cnt[NBUCKET];
        int t = threadIdx.x;
        int is64 = detect64(in_idx, E);
        for (int k = t; k < NBUCKET; k += 256) cnt[k] = 0;
        __syncthreads();
        int ch = (E + NEBLK - 1) / NEBLK;
        int s = b * ch, e = s + ch; if (e > E) e = E;
        for (int q = s + t; q < e; q += 256) {
            int o = fetch_idx(out_idx, q, is64);
            int i = fetch_idx(in_idx, q, is64);
            atomicAdd(&cnt[((o >> 7) << 5) | (i >> 6)], 1);
        }
        __syncthreads();
        for (int k = t; k < NBUCKET; k += 256) g_cntM[b][k] = cnt[k];
    }
}

// -------- 2. scan 512 bucket totals + per-edge-chunk cursors ----------------
__global__ void scan_kernel() {
    int t = threadIdx.x;            // 512 threads, one per bucket
    int lane = t & 31, wid = t >> 5;
    int s = 0;
#pragma unroll 8
    for (int b = 0; b < NEBLK; b++) s += g_cntM[b][t];

    int x = s;
#pragma unroll
    for (int d = 1; d < 32; d <<= 1) {
        int y = __shfl_up_sync(0xFFFFFFFFu, x, d);
        if (lane >= d) x += y;
    }
    __shared__ int ws[16];
    if (lane == 31) ws[wid] = x;
    __syncthreads();
    if (wid == 0 && lane < 16) {
        int v = ws[lane];
#pragma unroll
        for (int d = 1; d < 16; d <<= 1) {
            int y = __shfl_up_sync(0xFFFFu, v, d);
            if (lane >= d) v += y;
        }
        ws[lane] = v;
    }
    __syncthreads();
    int inc = x + (wid > 0 ? ws[wid - 1] : 0);
    int ex = inc - s;
    g_boff[t] = ex;
    if (t == 511) g_boff[NBUCKET] = inc;

    int run = ex;
#pragma unroll 8
    for (int b = 0; b < NEBLK; b++) { g_curM[b][t] = run; run += g_cntM[b][t]; }
}

// -------- 3. scatter packed edge records into bucket order ------------------
__global__ void __launch_bounds__(256) scatrec_kernel(
    const void* in_idx, const void* out_idx, const float* __restrict__ w, int E) {
    __shared__ int cur[NBUCKET];
    int b = blockIdx.x;
    int t = threadIdx.x;
    int is64 = detect64(in_idx, E);
    for (int k = t; k < NBUCKET; k += 256) cur[k] = g_curM[b][k];
    __syncthreads();
    int ch = (E + NEBLK - 1) / NEBLK;
    int s = b * ch, e = s + ch; if (e > E) e = E;
    for (int q = s + t; q < e; q += 256) {
        int o = fetch_idx(out_idx, q, is64);
        int i = fetch_idx(in_idx, q, is64);
        int key = ((o >> 7) << 5) | (i >> 6);
        int pos = atomicAdd(&cur[key], 1);
        unsigned hw = (unsigned)__half_as_ushort(__float2half_rn(w[q]));
        g_rec[pos] = ((unsigned)(o & 127) << 22) | ((unsigned)(i & 63) << 16) | hw;
    }
}

// -------- 4. GEMM with on-the-fly B densification in smem -------------------
// CTA = (n-group ng: 128 outs) x (m-tile: 128 batch). A: 3-stage cp.async.
// B: double-buffered 16KB tiles built per chunk from sorted edge records
// (zero + smem half2 atomicAdd). Compute: ldmatrix + mma.m16n8k16 fp32-acc.
__global__ void __launch_bounds__(256, 1) gemm_kernel(float* __restrict__ out) {
    extern __shared__ char smem[];
    uint32_t sb = smem_u32(smem);
    int t = threadIdx.x;
    int wid = t >> 5;
    int lane = t & 31;
    int ng = blockIdx.x;        // 0..15
    int m0 = blockIdx.y << 7;   // batch tile origin
    int n0 = ng << 7;
    int wm = (wid & 1) << 6;
    int wn = (wid >> 1) << 5;

    __shared__ int soff[NKC + 1];
    if (t <= NKC) soff[t] = g_boff[(ng << 5) + t];

    const __half* axh = g_xh + (size_t)m0 * IN_SIZE;

    auto loadA = [&](int kc, int st) {
        uint32_t stage = sb + st * TILEB;
        const __half* as = axh + kc * BK;
#pragma unroll
        for (int q = t; q < 1024; q += 256) {
            int r = q >> 3, sg = q & 7;
            CP_ASYNC16(stage + SWZ128((r << 7) + (sg << 4)),
                       as + (size_t)r * IN_SIZE + sg * 8);
        }
        CP_COMMIT();
    };

    char* bB0 = smem + SMEM_A;
    const __half hz = __ushort_as_half((unsigned short)0);

    auto buildB = [&](int c) {
        char* bb = bB0 + (c & 1) * TILEB;
#pragma unroll
        for (int q = t; q < 1024; q += 256)
            reinterpret_cast<uint4*>(bb)[q] = make_uint4(0, 0, 0, 0);
        __syncthreads();             // zero complete before placement
        int s = soff[c], e = soff[c + 1];
        for (int q = s + t; q < e; q += 256) {
            unsigned r = g_rec[q];
            int nl = r >> 22;
            int kl = (r >> 16) & 63;
            __half w = __ushort_as_half((unsigned short)(r & 0xFFFFu));
            uint32_t boff = (nl << 7) + ((kl & ~1) << 1);
            __half2* p = reinterpret_cast<__half2*>(bb + SWZ128(boff));
            __half2 v = (kl & 1) ? __halves2half2(hz, w) : __halves2half2(w, hz);
            atomicAdd(p, v);
        }
    };

    float c_[4][4][4];
#pragma unroll
    for (int a = 0; a < 4; a++)
#pragma unroll
        for (int b = 0; b < 4; b++)
#pragma unroll
            for (int k = 0; k < 4; k++) c_[a][b][k] = 0.f;

    loadA(0, 0);
    loadA(1, 1);
    buildB(0);                       // includes internal sync; soff visible after it

    int a_row = wm + (lane & 15);
    int a_kh = (lane >> 4) << 3;
    int b_row = wn + (lane & 7) + ((lane >> 4) << 3);
    int b_kh = ((lane >> 3) & 1) << 3;

    for (int ch = 0; ch < NKC; ch++) {
        CP_WAIT1();                  // A(ch) landed (A(ch+1) may be pending)
        __syncthreads();             // + B(ch) placement visible to all
        if (ch + 2 < NKC) loadA(ch + 2, (ch + 2) % A_STAGES);
        uint32_t sA = sb + (ch % A_STAGES) * TILEB;
        uint32_t sB = sb + SMEM_A + (ch & 1) * TILEB;
#pragma unroll
        for (int kk = 0; kk < BK; kk += 16) {
            uint32_t af[4][4], bf[2][4];
#pragma unroll
            for (int mi = 0; mi < 4; mi++) {
                uint32_t ad = sA + SWZ128(((a_row + (mi << 4)) << 7) +
                                          ((kk + a_kh) << 1));
                LDSM4(af[mi][0], af[mi][1], af[mi][2], af[mi][3], ad);
            }
#pragma unroll
            for (int nj = 0; nj < 2; nj++) {
                uint32_t bd = sB + SWZ128(((b_row + (nj << 4)) << 7) +
                                          ((kk + b_kh) << 1));
                LDSM4(bf[nj][0], bf[nj][1], bf[nj][2], bf[nj][3], bd);
            }
#pragma unroll
            for (int mi = 0; mi < 4; mi++)
#pragma unroll
                for (int j = 0; j < 4; j++)
                    MMA16816(c_[mi][j], af[mi],
                             bf[j >> 1][(j & 1) << 1],
                             bf[j >> 1][((j & 1) << 1) + 1]);
        }
        if (ch + 1 < NKC) buildB(ch + 1);  // other B buffer; overlaps nothing live
    }

    // epilogue: fp32 accumulators straight to d_out
    int rbase = m0 + wm + (lane >> 2);
    int cbase = n0 + wn + ((lane & 3) << 1);
#pragma unroll
    for (int mi = 0; mi < 4; mi++) {
#pragma unroll
        for (int j = 0; j < 4; j++) {
            int row = rbase + (mi << 4);
            int col = cbase + (j << 3);
            float* p0 = out + (size_t)row * OUT_SIZE + col;
            float* p1 = out + (size_t)(row + 8) * OUT_SIZE + col;
            p0[0] = c_[mi][j][0]; p0[1] = c_[mi][j][1];
            p1[0] = c_[mi][j][2]; p1[1] = c_[mi][j][3];
        }
    }
}

extern "C" void kernel_launch(void* const* d_in, const int* in_sizes, int n_in,
                              void* d_out, int out_size) {
    const float* x       = (const float*)d_in[0];
    const float* weights = (const float*)d_in[1];
    const void*  in_idx  = d_in[2];
    const void*  out_idx = d_in[3];
    float* out = (float*)d_out;
    int E = in_sizes[1];
    if (E > EMAX) E = EMAX;

    cudaFuncSetAttribute(gemm_kernel,
                         cudaFuncAttributeMaxDynamicSharedMemorySize, SMEM_TOTAL);

    prep_hist_kernel<<<512 + NEBLK, 256>>>(x, in_idx, out_idx, E);
    scan_kernel<<<1, 512>>>();
    scatrec_kernel<<<NEBLK, 256>>>(in_idx, out_idx, weights, E);

    dim3 grid(NG, BATCH / 128);   // 16 x 8 = 128 CTAs
    gemm_kernel<<<grid, 256, SMEM_TOTAL>>>(out);
}

// round 13
// speedup vs baseline: 1.7700x; 1.7700x over previous
#include <cuda_runtime.h>
#include <cuda_fp16.h>
#include <stdint.h>

// Problem constants (fixed by the reference)
#define BATCH 1024
#define IN_SIZE 2048
#define OUT_SIZE 2048
#define EMAX 131072

#define BK 64                           // halves per K chunk (128B = SW128 row)
#define NCHUNKS (IN_SIZE / BK)          // 32
#define TILE_BYTES 16384                // 128 rows x 128 bytes
#define STAGE_BYTES (2 * TILE_BYTES)    // A tile + B tile
#define NSTAGES 4
#define SMEM_TOTAL (NSTAGES * STAGE_BYTES)   // 128 KB

// -------- device scratch (no allocations allowed) --------
__device__ __half g_Wh[OUT_SIZE * IN_SIZE];    // 8 MB dense weights fp16 [out][in]
__device__ __half g_xh[BATCH * IN_SIZE];       // 4 MB x fp16 [batch][in]
__device__ int    g_idx64;

__device__ __forceinline__ int fetch_idx(const void* p, int e, int is64) {
    if (is64) return (int)(((const long long*)p)[e]);
    return ((const int*)p)[e];
}

// ---------------- helpers ----------------
__device__ __forceinline__ uint32_t smem_u32(const void* p) {
    uint32_t a;
    asm("{ .reg .u64 t; cvta.to.shared.u64 t, %1; cvt.u32.u64 %0, t; }"
        : "=r"(a) : "l"(p));
    return a;
}
#define SWZ128(off) ((off) ^ (((off) >> 3) & 0x70))
#define CP_ASYNC16(dst, src) \
    asm volatile("cp.async.cg.shared.global [%0], [%1], 16;" :: "r"(dst), "l"(src))
#define CP_COMMIT() asm volatile("cp.async.commit_group;" ::: "memory")
#define CP_WAIT2()  asm volatile("cp.async.wait_group 2;" ::: "memory")
#define LDSM4(r0, r1, r2, r3, a)                                               \
    asm volatile("ldmatrix.sync.aligned.m8n8.x4.shared.b16 {%0,%1,%2,%3}, [%4];" \
                 : "=r"(r0), "=r"(r1), "=r"(r2), "=r"(r3) : "r"(a))
#define MMA16816(c, a, b0, b1)                                                 \
    asm volatile(                                                              \
        "mma.sync.aligned.m16n8k16.row.col.f32.f16.f16.f32 "                   \
        "{%0,%1,%2,%3}, {%4,%5,%6,%7}, {%8,%9}, {%0,%1,%2,%3};"                \
        : "+f"(c[0]), "+f"(c[1]), "+f"(c[2]), "+f"(c[3])                       \
        : "r"(a[0]), "r"(a[1]), "r"(a[2]), "r"(a[3]), "r"(b0), "r"(b1))

// -------- 1. prep: zero Wh + convert x + detect idx dtype (fused, MLP-4) ----
// grid 512 x 256. Each thread: 4 independent float4 loads (batched -> MLP 4),
// 4 uint4 zeros of W, then the converted stores.
__global__ void __launch_bounds__(256) prep_kernel(const float* __restrict__ x,
                                                   const void* in_idx, int E) {
    int t = blockIdx.x * 256 + threadIdx.x;   // [0, 131072)

    float4 v[4];
#pragma unroll
    for (int r = 0; r < 4; r++)
        v[r] = reinterpret_cast<const float4*>(x)[t + r * 131072];

    uint4 z = make_uint4(0, 0, 0, 0);
#pragma unroll
    for (int r = 0; r < 4; r++)
        reinterpret_cast<uint4*>(g_Wh)[t + r * 131072] = z;

#pragma unroll
    for (int r = 0; r < 4; r++) {
        int q = t + r * 131072;
        __half2 h0 = __floats2half2_rn(v[r].x, v[r].y);
        __half2 h1 = __floats2half2_rn(v[r].z, v[r].w);
        reinterpret_cast<__half2*>(g_xh)[2 * q]     = h0;
        reinterpret_cast<__half2*>(g_xh)[2 * q + 1] = h1;
    }

    if (blockIdx.x == 0 && threadIdx.x < 32) {
        int lane = threadIdx.x;
        const long long* q = (const long long*)in_idx;
        long long vv = (lane < E) ? q[lane] : 0;
        bool bad = (vv < 0 || vv >= IN_SIZE);
        unsigned m = __ballot_sync(0xFFFFFFFFu, bad);
        if (lane == 0) g_idx64 = (m == 0) ? 1 : 0;
    }
}

// -------- 2. scatter-add weights into dense fp16 W (1 edge / thread) --------
__global__ void __launch_bounds__(256) scatter_w_kernel(
    const void* in_idx, const void* out_idx, const float* __restrict__ w, int E) {
    int e = blockIdx.x * 256 + threadIdx.x;
    if (e >= E) return;
    int is64 = g_idx64;
    int o = fetch_idx(out_idx, e, is64);
    int i = fetch_idx(in_idx, e, is64);
    int idx = o * IN_SIZE + i;
    const __half zero = __ushort_as_half((unsigned short)0);
    __half hw = __float2half_rn(w[e]);
    __half2* p = reinterpret_cast<__half2*>(g_Wh + (idx & ~1));
    __half2 v = (idx & 1) ? __halves2half2(zero, hw)
                          : __halves2half2(hw, zero);
    atomicAdd(p, v);
}

// -------- 3. GEMM: out[b][o] = sum_k xh[b][k] * Wh[o][k] --------------------
// CTA tile M128 x N128, 8 warps in 2x4 (64x32 per warp), BK=64, 4-stage
// cp.async pipeline (wait_group 2), ldmatrix + mma.m16n8k16, fp32 accum.
__global__ void __launch_bounds__(256, 1) gemm_kernel(float* __restrict__ out) {
    extern __shared__ char smem[];
    uint32_t sb = smem_u32(smem);
    int t = threadIdx.x;
    int wid = t >> 5;
    int lane = t & 31;
    int m0 = blockIdx.y << 7;   // batch tile origin
    int n0 = blockIdx.x << 7;   // out tile origin
    int wm = (wid & 1) << 6;    // warp m-origin within tile (0/64)
    int wn = (wid >> 1) << 5;   // warp n-origin within tile (0/32/64/96)

    const __half* axh = g_xh + (size_t)m0 * IN_SIZE;
    const __half* bwh = g_Wh + (size_t)n0 * IN_SIZE;

    // stage loader: chunk kc -> stage s. 2048 x 16B over 256 threads.
    auto load_tile = [&](int kc, int s) {
        uint32_t stage = sb + s * STAGE_BYTES;
        const __half* as = axh + kc * BK;
        const __half* bs = bwh + kc * BK;
#pragma unroll
        for (int q = t; q < 2048; q += 256) {
            int tile = q >> 10;           // 0=A, 1=B
            int r = (q >> 3) & 127;
            int sg = q & 7;
            uint32_t dst = stage + tile * TILE_BYTES + SWZ128((r << 7) + (sg << 4));
            const __half* src = (tile ? bs : as) + (size_t)r * IN_SIZE + sg * 8;
            CP_ASYNC16(dst, src);
        }
        CP_COMMIT();
    };

    float c[4][4][4];
#pragma unroll
    for (int a = 0; a < 4; a++)
#pragma unroll
        for (int b = 0; b < 4; b++)
#pragma unroll
            for (int k = 0; k < 4; k++) c[a][b][k] = 0.f;

    load_tile(0, 0);
    load_tile(1, 1);
    load_tile(2, 2);

    // per-lane ldmatrix address components (within-tile, pre-swizzle)
    int a_row = wm + (lane & 15);           // + mi*16
    int a_kh = (lane >> 4) << 3;            // + kk
    int b_row = wn + (lane & 7) + ((lane >> 4) << 3);  // + nj*16
    int b_kh = ((lane >> 3) & 1) << 3;      // + kk

    for (int ch = 0; ch < NCHUNKS; ch++) {
        CP_WAIT2();            // chunk ch landed; ch+1, ch+2 may be in flight
        __syncthreads();
        // stage (ch+3)%4 == (ch-1)%4: its MMAs completed before this barrier.
        if (ch + 3 < NCHUNKS) load_tile(ch + 3, (ch + 3) & 3);
        uint32_t sA = sb + (ch & 3) * STAGE_BYTES;
        uint32_t sB = sA + TILE_BYTES;
#pragma unroll
        for (int kk = 0; kk < BK; kk += 16) {
            uint32_t af[4][4], bf[2][4];
#pragma unroll
            for (int mi = 0; mi < 4; mi++) {
                uint32_t ad = sA + SWZ128(((a_row + (mi << 4)) << 7) +
                                          ((kk + a_kh) << 1));
                LDSM4(af[mi][0], af[mi][1], af[mi][2], af[mi][3], ad);
            }
#pragma unroll
            for (int nj = 0; nj < 2; nj++) {
                uint32_t bd = sB + SWZ128(((b_row + (nj << 4)) << 7) +
                                          ((kk + b_kh) << 1));
                LDSM4(bf[nj][0], bf[nj][1], bf[nj][2], bf[nj][3], bd);
            }
#pragma unroll
            for (int mi = 0; mi < 4; mi++)
#pragma unroll
                for (int j = 0; j < 4; j++)
                    MMA16816(c[mi][j], af[mi],
                             bf[j >> 1][(j & 1) << 1],
                             bf[j >> 1][((j & 1) << 1) + 1]);
        }
        __syncthreads();
    }

    // epilogue: write fp32 accumulators straight to d_out (float2 stores)
    int rbase = m0 + wm + (lane >> 2);
    int cbase = n0 + wn + ((lane & 3) << 1);
#pragma unroll
    for (int mi = 0; mi < 4; mi++) {
#pragma unroll
        for (int j = 0; j < 4; j++) {
            int row = rbase + (mi << 4);
            int col = cbase + (j << 3);
            *reinterpret_cast<float2*>(out + (size_t)row * OUT_SIZE + col) =
                make_float2(c[mi][j][0], c[mi][j][1]);
            *reinterpret_cast<float2*>(out + (size_t)(row + 8) * OUT_SIZE + col) =
                make_float2(c[mi][j][2], c[mi][j][3]);
        }
    }
}

extern "C" void kernel_launch(void* const* d_in, const int* in_sizes, int n_in,
                              void* d_out, int out_size) {
    const float* x       = (const float*)d_in[0];
    const float* weights = (const float*)d_in[1];
    const void*  in_idx  = d_in[2];
    const void*  out_idx = d_in[3];
    float* out = (float*)d_out;
    int E = in_sizes[1];
    if (E > EMAX) E = EMAX;

    cudaFuncSetAttribute(gemm_kernel,
                         cudaFuncAttributeMaxDynamicSharedMemorySize, SMEM_TOTAL);

    // 1. fused prep: zero W (8 MB) + convert x (fp32->fp16) + dtype detect
    prep_kernel<<<512, 256>>>(x, in_idx, E);

    // 2. scatter-add edge weights into dense fp16 W
    scatter_w_kernel<<<(EMAX + 255) / 256, 256>>>(in_idx, out_idx, weights, E);

    // 3. tensor-core GEMM, epilogue writes d_out directly
    dim3 grid(OUT_SIZE / 128, BATCH / 128);  // 16 x 8 = 128 CTAs
    gemm_kernel<<<grid, 256, SMEM_TOTAL>>>(out);
}

// round 14
// speedup vs baseline: 1.8792x; 1.0617x over previous
#include <cuda_runtime.h>
#include <cuda_fp16.h>
#include <stdint.h>

// Problem constants (fixed by the reference)
#define BATCH 1024
#define IN_SIZE 2048
#define OUT_SIZE 2048
#define EMAX 131072

#define BK 64                           // halves per K chunk (128B = SW128 row)
#define NCHUNKS (IN_SIZE / BK)          // 32
#define A_TILE_BYTES 8192               // 64 rows x 128 bytes
#define B_TILE_BYTES 16384              // 128 rows x 128 bytes
#define STAGE_BYTES (A_TILE_BYTES + B_TILE_BYTES)   // 24 KB
#define NSTAGES 3
#define SMEM_TOTAL (NSTAGES * STAGE_BYTES)          // 72 KB -> 2 CTAs/SM

// -------- device scratch (no allocations allowed) --------
__device__ __half g_Wh[OUT_SIZE * IN_SIZE];    // 8 MB dense weights fp16 [out][in]
__device__ __half g_xh[BATCH * IN_SIZE];       // 4 MB x fp16 [batch][in]
__device__ int    g_idx64;

__device__ __forceinline__ int fetch_idx(const void* p, int e, int is64) {
    if (is64) return (int)(((const long long*)p)[e]);
    return ((const int*)p)[e];
}

// ---------------- helpers ----------------
__device__ __forceinline__ uint32_t smem_u32(const void* p) {
    uint32_t a;
    asm("{ .reg .u64 t; cvta.to.shared.u64 t, %1; cvt.u32.u64 %0, t; }"
        : "=r"(a) : "l"(p));
    return a;
}
#define SWZ128(off) ((off) ^ (((off) >> 3) & 0x70))
#define CP_ASYNC16(dst, src) \
    asm volatile("cp.async.cg.shared.global [%0], [%1], 16;" :: "r"(dst), "l"(src))
#define CP_COMMIT() asm volatile("cp.async.commit_group;" ::: "memory")
#define CP_WAIT1()  asm volatile("cp.async.wait_group 1;" ::: "memory")
#define LDSM4(r0, r1, r2, r3, a)                                               \
    asm volatile("ldmatrix.sync.aligned.m8n8.x4.shared.b16 {%0,%1,%2,%3}, [%4];" \
                 : "=r"(r0), "=r"(r1), "=r"(r2), "=r"(r3) : "r"(a))
#define MMA16816(c, a, b0, b1)                                                 \
    asm volatile(                                                              \
        "mma.sync.aligned.m16n8k16.row.col.f32.f16.f16.f32 "                   \
        "{%0,%1,%2,%3}, {%4,%5,%6,%7}, {%8,%9}, {%0,%1,%2,%3};"                \
        : "+f"(c[0]), "+f"(c[1]), "+f"(c[2]), "+f"(c[3])                       \
        : "r"(a[0]), "r"(a[1]), "r"(a[2]), "r"(a[3]), "r"(b0), "r"(b1))

// -------- 1. prep: zero Wh + convert x + detect idx dtype (fused) -----------
// 2048 blocks x 256 thr (the measured-best variant from R8).
__global__ void __launch_bounds__(256) prep_kernel(const float* __restrict__ x,
                                                   const void* in_idx, int E) {
    int t = blockIdx.x * blockDim.x + threadIdx.x;

    // zero W: 4M halves = 512K uint4
    reinterpret_cast<uint4*>(g_Wh)[t] = make_uint4(0, 0, 0, 0);

    // convert x: 2M floats = 512K float4 -> 512K (half2,half2)
    float4 v = reinterpret_cast<const float4*>(x)[t];
    __half2 h0 = __floats2half2_rn(v.x, v.y);
    __half2 h1 = __floats2half2_rn(v.z, v.w);
    reinterpret_cast<__half2*>(g_xh)[2 * t]     = h0;
    reinterpret_cast<__half2*>(g_xh)[2 * t + 1] = h1;

    if (blockIdx.x == 0 && threadIdx.x < 32) {
        int lane = threadIdx.x;
        const long long* q = (const long long*)in_idx;
        long long vv = (lane < E) ? q[lane] : 0;
        bool bad = (vv < 0 || vv >= IN_SIZE);
        unsigned m = __ballot_sync(0xFFFFFFFFu, bad);
        if (lane == 0) g_idx64 = (m == 0) ? 1 : 0;
    }
}

// -------- 2. scatter-add weights into dense fp16 W (1 edge / thread) --------
__global__ void __launch_bounds__(256) scatter_w_kernel(
    const void* in_idx, const void* out_idx, const float* __restrict__ w, int E) {
    int e = blockIdx.x * 256 + threadIdx.x;
    if (e >= E) return;
    int is64 = g_idx64;
    int o = fetch_idx(out_idx, e, is64);
    int i = fetch_idx(in_idx, e, is64);
    int idx = o * IN_SIZE + i;
    const __half zero = __ushort_as_half((unsigned short)0);
    __half hw = __float2half_rn(w[e]);
    __half2* p = reinterpret_cast<__half2*>(g_Wh + (idx & ~1));
    __half2 v = (idx & 1) ? __halves2half2(zero, hw)
                          : __halves2half2(hw, zero);
    atomicAdd(p, v);
}

// -------- 3. GEMM: out[b][o] = sum_k xh[b][k] * Wh[o][k] --------------------
// CTA tile M64 x N128 (256 CTAs, 2 CTAs/SM co-resident), 8 warps in 2x4
// (32x32 per warp), BK=64, 3-stage cp.async pipeline, mma.m16n8k16 fp32-acc.
__global__ void __launch_bounds__(256, 2) gemm_kernel(float* __restrict__ out) {
    extern __shared__ char smem[];
    uint32_t sb = smem_u32(smem);
    int t = threadIdx.x;
    int wid = t >> 5;
    int lane = t & 31;
    int m0 = blockIdx.y << 6;   // batch tile origin (64 rows)
    int n0 = blockIdx.x << 7;   // out tile origin (128 cols)
    int wm = (wid & 1) << 5;    // warp m-origin (0/32)
    int wn = (wid >> 1) << 5;   // warp n-origin (0/32/64/96)

    const __half* axh = g_xh + (size_t)m0 * IN_SIZE;
    const __half* bwh = g_Wh + (size_t)n0 * IN_SIZE;

    // stage loader: 512 A-ops + 1024 B-ops of 16B over 256 threads (6 each)
    auto load_tile = [&](int kc, int s) {
        uint32_t stage = sb + s * STAGE_BYTES;
        const __half* as = axh + kc * BK;
        const __half* bs = bwh + kc * BK;
#pragma unroll
        for (int q = t; q < 1536; q += 256) {
            if (q < 512) {
                int r = q >> 3, sg = q & 7;
                CP_ASYNC16(stage + SWZ128((r << 7) + (sg << 4)),
                           as + (size_t)r * IN_SIZE + sg * 8);
            } else {
                int q2 = q - 512;
                int r = q2 >> 3, sg = q2 & 7;
                CP_ASYNC16(stage + A_TILE_BYTES + SWZ128((r << 7) + (sg << 4)),
                           bs + (size_t)r * IN_SIZE + sg * 8);
            }
        }
        CP_COMMIT();
    };

    float c[2][4][4];
#pragma unroll
    for (int a = 0; a < 2; a++)
#pragma unroll
        for (int b = 0; b < 4; b++)
#pragma unroll
            for (int k = 0; k < 4; k++) c[a][b][k] = 0.f;

    load_tile(0, 0);
    load_tile(1, 1);

    // per-lane ldmatrix address components (within-tile, pre-swizzle)
    int a_row = wm + (lane & 15);                      // + mi*16
    int a_kh = (lane >> 4) << 3;
    int b_row = wn + (lane & 7) + ((lane >> 4) << 3);  // + nj*16
    int b_kh = ((lane >> 3) & 1) << 3;

    for (int ch = 0; ch < NCHUNKS; ch++) {
        CP_WAIT1();            // chunk ch landed; ch+1 may be in flight
        __syncthreads();
        if (ch + 2 < NCHUNKS) load_tile(ch + 2, (ch + 2) % NSTAGES);
        uint32_t sA = sb + (ch % NSTAGES) * STAGE_BYTES;
        uint32_t sB = sA + A_TILE_BYTES;
#pragma unroll
        for (int kk = 0; kk < BK; kk += 16) {
            uint32_t af[2][4], bf[2][4];
#pragma unroll
            for (int mi = 0; mi < 2; mi++) {
                uint32_t ad = sA + SWZ128(((a_row + (mi << 4)) << 7) +
                                          ((kk + a_kh) << 1));
                LDSM4(af[mi][0], af[mi][1], af[mi][2], af[mi][3], ad);
            }
#pragma unroll
            for (int nj = 0; nj < 2; nj++) {
                uint32_t bd = sB + SWZ128(((b_row + (nj << 4)) << 7) +
                                          ((kk + b_kh) << 1));
                LDSM4(bf[nj][0], bf[nj][1], bf[nj][2], bf[nj][3], bd);
            }
#pragma unroll
            for (int mi = 0; mi < 2; mi++)
#pragma unroll
                for (int j = 0; j < 4; j++)
                    MMA16816(c[mi][j], af[mi],
                             bf[j >> 1][(j & 1) << 1],
                             bf[j >> 1][((j & 1) << 1) + 1]);
        }
        __syncthreads();
    }

    // epilogue: write fp32 accumulators straight to d_out (float2 stores)
    int rbase = m0 + wm + (lane >> 2);
    int cbase = n0 + wn + ((lane & 3) << 1);
#pragma unroll
    for (int mi = 0; mi < 2; mi++) {
#pragma unroll
        for (int j = 0; j < 4; j++) {
            int row = rbase + (mi << 4);
            int col = cbase + (j << 3);
            *reinterpret_cast<float2*>(out + (size_t)row * OUT_SIZE + col) =
                make_float2(c[mi][j][0], c[mi][j][1]);
            *reinterpret_cast<float2*>(out + (size_t)(row + 8) * OUT_SIZE + col) =
                make_float2(c[mi][j][2], c[mi][j][3]);
        }
    }
}

extern "C" void kernel_launch(void* const* d_in, const int* in_sizes, int n_in,
                              void* d_out, int out_size) {
    const float* x       = (const float*)d_in[0];
    const float* weights = (const float*)d_in[1];
    const void*  in_idx  = d_in[2];
    const void*  out_idx = d_in[3];
    float* out = (float*)d_out;
    int E = in_sizes[1];
    if (E > EMAX) E = EMAX;

    cudaFuncSetAttribute(gemm_kernel,
                         cudaFuncAttributeMaxDynamicSharedMemorySize, SMEM_TOTAL);

    // 1. fused prep: zero W (8 MB) + convert x (fp32->fp16) + dtype detect
    prep_kernel<<<2048, 256>>>(x, in_idx, E);

    // 2. scatter-add edge weights into dense fp16 W
    scatter_w_kernel<<<(EMAX + 255) / 256, 256>>>(in_idx, out_idx, weights, E);

    // 3. tensor-core GEMM, 256 CTAs (2 co-resident per SM)
    dim3 grid(OUT_SIZE / 128, BATCH / 64);  // 16 x 16 = 256 CTAs
    gemm_kernel<<<grid, 256, SMEM_TOTAL>>>(out);
}